// round 1
// baseline (speedup 1.0000x reference)
#include <cuda_runtime.h>

#define N_NODES 4096
#define HIDDEN  64
#define N_REL   8
#define N_LAYERS 2
#define NH (N_NODES * HIDDEN)

// Scratch (device globals — no allocation allowed)
__device__ float g_h[2][NH];        // ping-pong hidden state
__device__ float g_Y[N_REL][NH];    // per-relation h @ w_rel[l,r]
__device__ float g_S[NH];           // h @ w_self[l]
__device__ float g_part[N_REL][NH]; // split-K partials

// ---------------------------------------------------------------------------
// init: copy node_embed[:4096] into g_h[0]
// ---------------------------------------------------------------------------
__global__ void copy_init_kernel(float* __restrict__ dst, const float* __restrict__ src) {
    int i = blockIdx.x * blockDim.x + threadIdx.x;
    if (i < NH / 4) ((float4*)dst)[i] = ((const float4*)src)[i];
}

// ---------------------------------------------------------------------------
// compute Y_r = h @ w_rel[l,r]  (blockIdx.y = 0..7)  and  S = h @ w_self[l]
// (blockIdx.y = 8). Block handles a 64-row m-tile.
// ---------------------------------------------------------------------------
__global__ void __launch_bounds__(256) compute_ys_kernel(
    const float* __restrict__ h,
    const float* __restrict__ w_self,
    const float* __restrict__ w_rel,
    int layer, float* __restrict__ Y, float* __restrict__ S)
{
    __shared__ float Ws[HIDDEN * HIDDEN];
    __shared__ float Hs[64 * HIDDEN];

    int m0 = blockIdx.x * 64;
    int wi = blockIdx.y;
    const float* W = (wi < N_REL)
        ? (w_rel + ((size_t)layer * N_REL + wi) * HIDDEN * HIDDEN)
        : (w_self + (size_t)layer * HIDDEN * HIDDEN);
    float* out = (wi < N_REL)
        ? (Y + (size_t)wi * NH + (size_t)m0 * HIDDEN)
        : (S + (size_t)m0 * HIDDEN);

    int tid = threadIdx.x;
    const float4* Wg = (const float4*)W;
    const float4* Hg = (const float4*)(h + (size_t)m0 * HIDDEN);
    for (int i = tid; i < 1024; i += 256) {
        ((float4*)Ws)[i] = Wg[i];
        ((float4*)Hs)[i] = Hg[i];
    }
    __syncthreads();

    int tx = tid & 15, ty = tid >> 4;
    int e0 = tx * 4;
    #pragma unroll
    for (int mi = 0; mi < 4; mi++) {
        int m = ty * 4 + mi;
        float4 acc = make_float4(0.f, 0.f, 0.f, 0.f);
        #pragma unroll
        for (int d = 0; d < HIDDEN; d++) {
            float hv = Hs[m * HIDDEN + d];
            float4 wv = *(const float4*)&Ws[d * HIDDEN + e0];
            acc.x = fmaf(hv, wv.x, acc.x);
            acc.y = fmaf(hv, wv.y, acc.y);
            acc.z = fmaf(hv, wv.z, acc.z);
            acc.w = fmaf(hv, wv.w, acc.w);
        }
        *(float4*)&out[m * HIDDEN + e0] = acc;
    }
}

// ---------------------------------------------------------------------------
// Main GEMM, split-K over relations:
//   part[r][n][e] = sum_m adj[r][n][m] * Y[r][m][e]
// Block tile: 64(n) x 64(e), TK=16, 256 threads, 4x4 micro-tile.
// Grid: (64 n-tiles, 8 relations) = 512 blocks.
// ---------------------------------------------------------------------------
#define TK 16
__global__ void __launch_bounds__(256) gemm_part_kernel(
    const float* __restrict__ adj,
    const float* __restrict__ Yall,
    float* __restrict__ part)
{
    __shared__ float As[TK][68];   // transposed: As[k][n_local]; 68 pad keeps 16B align
    __shared__ float Bs[TK][64];   // Bs[k][e]

    int n0 = blockIdx.x * 64;
    int r  = blockIdx.y;
    const float* A = adj  + (size_t)r * N_NODES * N_NODES;
    const float* B = Yall + (size_t)r * NH;

    int tid = threadIdx.x;
    int tx = tid & 15, ty = tid >> 4;
    int arow = tid >> 2,  acol = (tid & 3) * 4;    // A loader: 64 rows x 16 k
    int brow = tid >> 4,  bcol = (tid & 15) * 4;   // B loader: 16 k x 64 e

    const float* Aptr = A + (size_t)(n0 + arow) * N_NODES + acol;
    const float* Bptr = B + (size_t)brow * HIDDEN + bcol;

    float acc[4][4];
    #pragma unroll
    for (int i = 0; i < 4; i++)
        #pragma unroll
        for (int j = 0; j < 4; j++) acc[i][j] = 0.f;

    for (int mt = 0; mt < N_NODES; mt += TK) {
        float4 av = *(const float4*)(Aptr + mt);
        float4 bv = *(const float4*)(Bptr + (size_t)mt * HIDDEN);
        __syncthreads();
        As[acol + 0][arow] = av.x;
        As[acol + 1][arow] = av.y;
        As[acol + 2][arow] = av.z;
        As[acol + 3][arow] = av.w;
        *(float4*)&Bs[brow][bcol] = bv;
        __syncthreads();
        #pragma unroll
        for (int k = 0; k < TK; k++) {
            float4 a = *(const float4*)&As[k][ty * 4];
            float4 b = *(const float4*)&Bs[k][tx * 4];
            acc[0][0] = fmaf(a.x, b.x, acc[0][0]);
            acc[0][1] = fmaf(a.x, b.y, acc[0][1]);
            acc[0][2] = fmaf(a.x, b.z, acc[0][2]);
            acc[0][3] = fmaf(a.x, b.w, acc[0][3]);
            acc[1][0] = fmaf(a.y, b.x, acc[1][0]);
            acc[1][1] = fmaf(a.y, b.y, acc[1][1]);
            acc[1][2] = fmaf(a.y, b.z, acc[1][2]);
            acc[1][3] = fmaf(a.y, b.w, acc[1][3]);
            acc[2][0] = fmaf(a.z, b.x, acc[2][0]);
            acc[2][1] = fmaf(a.z, b.y, acc[2][1]);
            acc[2][2] = fmaf(a.z, b.z, acc[2][2]);
            acc[2][3] = fmaf(a.z, b.w, acc[2][3]);
            acc[3][0] = fmaf(a.w, b.x, acc[3][0]);
            acc[3][1] = fmaf(a.w, b.y, acc[3][1]);
            acc[3][2] = fmaf(a.w, b.z, acc[3][2]);
            acc[3][3] = fmaf(a.w, b.w, acc[3][3]);
        }
    }

    float* P = part + (size_t)r * NH;
    #pragma unroll
    for (int i = 0; i < 4; i++) {
        int row = n0 + ty * 4 + i;
        float4 v = make_float4(acc[i][0], acc[i][1], acc[i][2], acc[i][3]);
        *(float4*)&P[(size_t)row * HIDDEN + tx * 4] = v;
    }
}

// ---------------------------------------------------------------------------
// finish: h_next = relu(S + sum_r part[r])
// ---------------------------------------------------------------------------
__global__ void finish_kernel(const float* __restrict__ S,
                              const float* __restrict__ part,
                              float* __restrict__ hn)
{
    int i = blockIdx.x * blockDim.x + threadIdx.x;
    if (i < NH) {
        float v = S[i];
        #pragma unroll
        for (int r = 0; r < N_REL; r++) v += part[(size_t)r * NH + i];
        hn[i] = fmaxf(v, 0.f);
    }
}

// ---------------------------------------------------------------------------
// gather: out[k][e] = (id < 4096) ? h[id][e] : 0   (id==4096 is the pad row)
// ---------------------------------------------------------------------------
__global__ void gather_kernel(const float* __restrict__ h,
                              const int* __restrict__ ids,
                              float* __restrict__ out)
{
    int k = blockIdx.x;          // 0..2047 keyword slots
    int e = threadIdx.x;         // 0..63
    int id = ids[k];
    float v = (id < N_NODES) ? h[(size_t)id * HIDDEN + e] : 0.f;
    out[(size_t)k * HIDDEN + e] = v;
}

// ---------------------------------------------------------------------------
extern "C" void kernel_launch(void* const* d_in, const int* in_sizes, int n_in,
                              void* d_out, int out_size)
{
    const float* node_embed  = (const float*)d_in[0];
    const float* w_self      = (const float*)d_in[1];
    const float* w_rel       = (const float*)d_in[2];
    const float* rel_adj     = (const float*)d_in[3];
    const int*   keyword_ids = (const int*)d_in[4];
    float* out = (float*)d_out;

    float *h_base, *y_base, *s_base, *p_base;
    cudaGetSymbolAddress((void**)&h_base, g_h);
    cudaGetSymbolAddress((void**)&y_base, g_Y);
    cudaGetSymbolAddress((void**)&s_base, g_S);
    cudaGetSymbolAddress((void**)&p_base, g_part);

    copy_init_kernel<<<NH / 4 / 256, 256>>>(h_base, node_embed);

    for (int l = 0; l < N_LAYERS; l++) {
        float* hc = h_base + (size_t)(l & 1) * NH;
        float* hn = h_base + (size_t)((l + 1) & 1) * NH;
        compute_ys_kernel<<<dim3(64, 9), 256>>>(hc, w_self, w_rel, l, y_base, s_base);
        gemm_part_kernel<<<dim3(64, N_REL), 256>>>(rel_adj, y_base, p_base);
        finish_kernel<<<NH / 256, 256>>>(s_base, p_base, hn);
    }

    // after 2 layers, final h is back in g_h[0]
    gather_kernel<<<2048, 64>>>(h_base, keyword_ids, out);
}